// round 3
// baseline (speedup 1.0000x reference)
#include <cuda_runtime.h>
#include <cuda_bf16.h>
#include <math_constants.h>

// Scratch: exclusive-prefix starts for up to 64K segments (allocation-free rule).
__device__ int g_starts[1 << 16];

#define SCAN_T 1024

// Single-block exclusive prefix-sum of int32 sizes -> g_starts.
__global__ void scan_sizes_kernel(const int* __restrict__ sizes, int n) {
    __shared__ int s[SCAN_T];
    const int t = threadIdx.x;
    int offset = 0;
    for (int base = 0; base < n; base += 2 * SCAN_T) {
        const int i0 = base + 2 * t;
        const int i1 = base + 2 * t + 1;
        const int a0 = (i0 < n) ? sizes[i0] : 0;
        const int a1 = (i1 < n) ? sizes[i1] : 0;
        s[t] = a0 + a1;
        __syncthreads();
        #pragma unroll
        for (int d = 1; d < SCAN_T; d <<= 1) {
            const int v = (t >= d) ? s[t - d] : 0;
            __syncthreads();
            s[t] += v;
            __syncthreads();
        }
        const int excl = (t > 0) ? s[t - 1] : 0;
        if (i0 < n) g_starts[i0] = offset + excl;
        if (i1 < n) g_starts[i1] = offset + excl + a0;
        const int chunk_total = s[SCAN_T - 1];
        __syncthreads();
        offset += chunk_total;
    }
}

__device__ __forceinline__ float4 fmax4(float4 a, float4 b) {
    a.x = fmaxf(a.x, b.x);
    a.y = fmaxf(a.y, b.y);
    a.z = fmaxf(a.z, b.z);
    a.w = fmaxf(a.w, b.w);
    return a;
}

// One CTA per segment. 256 threads = 8 row-groups x 32 float4-columns (D=128).
// Warp w reduces rows {w, w+8, w+16, ...} of the segment's first m rows,
// each warp-iteration loading one fully-coalesced 512B row.
__global__ void __launch_bounds__(256, 8)
seg_prefix_max_kernel(const float* __restrict__ x,
                      const int* __restrict__ sizes,
                      const int* __restrict__ wptr,
                      float* __restrict__ out) {
    const int seg = blockIdx.x;
    const int start = g_starts[seg];
    const int w = *wptr;
    const int m = sizes[seg] - w + 1;

    const int tid  = threadIdx.x;
    const int c4   = tid & 31;   // float4 column 0..31
    const int rgrp = tid >> 5;   // row group 0..7

    const float4* __restrict__ base =
        reinterpret_cast<const float4*>(x) + (size_t)start * 32;

    float4 acc = make_float4(-CUDART_INF_F, -CUDART_INF_F,
                             -CUDART_INF_F, -CUDART_INF_F);

    // Main unrolled loop: 4 independent rows in flight per thread (MLP).
    int r = rgrp;
    for (; r + 24 < m; r += 32) {
        const float4 v0 = base[(r      ) * 32 + c4];
        const float4 v1 = base[(r +  8) * 32 + c4];
        const float4 v2 = base[(r + 16) * 32 + c4];
        const float4 v3 = base[(r + 24) * 32 + c4];
        acc = fmax4(acc, fmax4(fmax4(v0, v1), fmax4(v2, v3)));
    }
    for (; r < m; r += 8) {
        acc = fmax4(acc, base[r * 32 + c4]);
    }

    // Reduce the 8 row-groups down to 1 via shared memory.
    __shared__ float4 sm[256];
    sm[tid] = acc;
    __syncthreads();
    if (tid < 128) sm[tid] = fmax4(sm[tid], sm[tid + 128]);
    __syncthreads();
    if (tid < 64)  sm[tid] = fmax4(sm[tid], sm[tid + 64]);
    __syncthreads();
    if (tid < 32) {
        const float4 res = fmax4(sm[tid], sm[tid + 32]);
        reinterpret_cast<float4*>(out)[seg * 32 + c4] = res;
    }
}

extern "C" void kernel_launch(void* const* d_in, const int* in_sizes, int n_in,
                              void* d_out, int out_size) {
    const float* x     = (const float*)d_in[0];
    const int*   sizes = (const int*)d_in[1];
    const int*   wptr  = (const int*)d_in[2];
    float*       out   = (float*)d_out;

    const int n_seg = in_sizes[1];

    scan_sizes_kernel<<<1, SCAN_T>>>(sizes, n_seg);
    seg_prefix_max_kernel<<<n_seg, 256>>>(x, sizes, wptr, out);
}